// round 2
// baseline (speedup 1.0000x reference)
#include <cuda_runtime.h>

// warp3D: out[b,c,z,y,x] = trilinear gather of I at (x+fx, y+fy, z+fz)
// Shapes fixed: B=2, C=2, D=160, H=192, W=224, fp32.
//
// Two-kernel plan:
//  1) transpose I [B,C,D,H,W] -> It [B,D,H,W,C] (float2 per voxel, streaming)
//  2) warp kernel gathers 8x float2 corners (channels packed) instead of
//     16x float — halves L1tex wavefronts and halves cached I footprint.

#define Wd 224
#define Hd 192
#define Dd 160
#define Bd 2
#define Cd 2
#define HWd (Hd * Wd)          // 43008
#define DHWd (Dd * HWd)        // 6881280

// Channel-packed copy of I: It[b*DHW + s] = {I[b,0,s], I[b,1,s]}  (~110 MB)
__device__ float2 g_It[(long)Bd * DHWd];

__global__ __launch_bounds__(256) void pack_channels_kernel(
    const float* __restrict__ I)
{
    const long s = (long)blockIdx.x * 256 + threadIdx.x;   // 0..DHW-1
    const long b = blockIdx.y;
    const float* __restrict__ Ib = I + b * (long)Cd * DHWd;
    float2 v;
    v.x = Ib[s];
    v.y = Ib[s + DHWd];
    g_It[b * (long)DHWd + s] = v;
}

__global__ __launch_bounds__(Wd) void warp3d_kernel(
    const float* __restrict__ flow,
    float* __restrict__ out)
{
    const int x = threadIdx.x;     // 0..223
    const int y = blockIdx.x;      // 0..191
    const int z = blockIdx.y;      // 0..159
    const int b = blockIdx.z;      // 0..1

    const long s = (long)z * HWd + (long)y * Wd + x;

    // flow[b, ch, z, y, x] — coalesced streams
    const float* __restrict__ fb = flow + (long)b * 3 * DHWd + s;
    const float fx = __ldg(fb);
    const float fy = __ldg(fb + DHWd);
    const float fz = __ldg(fb + 2L * DHWd);

    const float xs = fx + (float)x;
    const float ys = fy + (float)y;
    const float zs = fz + (float)z;

    int x0 = (int)floorf(xs);
    int y0 = (int)floorf(ys);
    int z0 = (int)floorf(zs);
    // Order matters: x1 from UNclamped x0+1, then clamp both (matches ref).
    int x1 = min(max(x0 + 1, 0), Wd - 1);
    int y1 = min(max(y0 + 1, 0), Hd - 1);
    int z1 = min(max(z0 + 1, 0), Dd - 1);
    x0 = min(max(x0, 0), Wd - 1);
    y0 = min(max(y0, 0), Hd - 1);
    z0 = min(max(z0, 0), Dd - 1);

    // Weights use the CLAMPED upper corner (matches reference).
    const float dx = (float)x1 - xs;
    const float dy = (float)y1 - ys;
    const float dz = (float)z1 - zs;
    const float ex = 1.0f - dx;
    const float ey = 1.0f - dy;
    const float ez = 1.0f - dz;

    const float w00 = dx * dy;   // (y0,x0)
    const float w10 = dx * ey;   // (y1,x0)
    const float w01 = ex * dy;   // (y0,x1)
    const float w11 = ex * ey;   // (y1,x1)

    const int r00 = z0 * HWd + y0 * Wd;
    const int r10 = z0 * HWd + y1 * Wd;
    const int r01 = z1 * HWd + y0 * Wd;
    const int r11 = z1 * HWd + y1 * Wd;

    const float2* __restrict__ Ic = g_It + (long)b * DHWd;

    // 8 channel-packed corner gathers (LDG.64 each)
    const float2 a0 = __ldg(Ic + r00 + x0);
    const float2 a1 = __ldg(Ic + r10 + x0);
    const float2 a2 = __ldg(Ic + r00 + x1);
    const float2 a3 = __ldg(Ic + r10 + x1);
    const float2 b0 = __ldg(Ic + r01 + x0);
    const float2 b1 = __ldg(Ic + r11 + x0);
    const float2 b2 = __ldg(Ic + r01 + x1);
    const float2 b3 = __ldg(Ic + r11 + x1);

    // z0-plane bilinear, both channels
    float p0x = w00 * a0.x + w10 * a1.x + w01 * a2.x + w11 * a3.x;
    float p0y = w00 * a0.y + w10 * a1.y + w01 * a2.y + w11 * a3.y;
    // z1-plane bilinear
    float p1x = w00 * b0.x + w10 * b1.x + w01 * b2.x + w11 * b3.x;
    float p1y = w00 * b0.y + w10 * b1.y + w01 * b2.y + w11 * b3.y;

    float* __restrict__ ob = out + (long)b * Cd * DHWd + s;
    ob[0]    = dz * p0x + ez * p1x;
    ob[DHWd] = dz * p0y + ez * p1y;
}

extern "C" void kernel_launch(void* const* d_in, const int* in_sizes, int n_in,
                              void* d_out, int out_size)
{
    const float* I    = (const float*)d_in[0];
    const float* flow = (const float*)d_in[1];
    float* out        = (float*)d_out;

    // 1) pack channels: DHW/256 = 26880 blocks per batch
    dim3 pgrid(DHWd / 256, Bd, 1);
    pack_channels_kernel<<<pgrid, 256>>>(I);

    // 2) warp
    dim3 block(Wd, 1, 1);         // 224 = 7 warps
    dim3 grid(Hd, Dd, Bd);        // 192 x 160 x 2
    warp3d_kernel<<<grid, block>>>(flow, out);
}